// round 9
// baseline (speedup 1.0000x reference)
#include <cuda_runtime.h>

using ull = unsigned long long;

// ---------- packed f32x2 + MUFU helpers ----------
__device__ __forceinline__ ull pk2(float lo, float hi) {
    ull r; asm("mov.b64 %0, {%1, %2};" : "=l"(r) : "f"(lo), "f"(hi)); return r;
}
__device__ __forceinline__ void upk2(ull v, float& lo, float& hi) {
    asm("mov.b64 {%0, %1}, %2;" : "=f"(lo), "=f"(hi) : "l"(v));
}
__device__ __forceinline__ ull fma2(ull a, ull b, ull c) {
    ull d; asm("fma.rn.f32x2 %0, %1, %2, %3;" : "=l"(d) : "l"(a), "l"(b), "l"(c)); return d;
}
__device__ __forceinline__ float tanhf_hw(float x) {
    float y; asm("tanh.approx.f32 %0, %1;" : "=f"(y) : "f"(x)); return y;
}

#define HID 10

// ONE batch element per 32-lane warp -> 4096 warps = ~6.9/SMSP (3x previous),
// which is the only lever that has moved this kernel. Work spread over lanes:
//   lanes 0-9 : packed (i,f) gate rows for hidden unit j=lane
//   lanes 10-19: packed (g,o) gate rows for unit j=lane-10
//   lane 20   : fc output head fused as an extra "gate row" (one step delayed)
//   lanes 21-31: dead (zero weights)
// Per step: 11 fma2 (all 40 gates + head), 2 MUFU + 2 FMA activations
// (per-lane consts), 2 SHFL.down to pair (g,o) with (i,f), 5-inst cell,
// h republished as duplicated pairs: 1 STS.64 + syncwarp + 5 broadcast
// LDS.128 (ping-pong buffers, one sync per step).
__global__ void __launch_bounds__(32, 28)
lstm_wide_kernel(const float* __restrict__ x,
                 const float* __restrict__ w_ih,
                 const float* __restrict__ w_hh,
                 const float* __restrict__ b_ih,
                 const float* __restrict__ b_hh,
                 const float* __restrict__ fc_w,
                 const float* __restrict__ fc_b,
                 float* __restrict__ out,
                 int S, int B)
{
    __shared__ float4 hbuf[2][5];   // duplicated h pairs: (h0,h0,h1,h1,...)

    const int lane = threadIdx.x;   // 32-thread blocks
    const int b    = blockIdx.x;    // one element per block/warp

    // ---- per-lane packed row weights ----
    ull w2[HID], wxb = 0ull, bb = 0ull;
    float Alo = 0.5f, Blo = 0.5f;   // lo-side activation consts
#pragma unroll
    for (int k = 0; k < HID; ++k) w2[k] = 0ull;

    if (lane < 10) {                // (i,f) rows, 0.5 sigmoid-fold
        const int j = lane;
#pragma unroll
        for (int k = 0; k < HID; ++k)
            w2[k] = pk2(0.5f * w_hh[j * HID + k],
                        0.5f * w_hh[(HID + j) * HID + k]);
        wxb = pk2(0.5f * w_ih[j], 0.5f * w_ih[HID + j]);
        bb  = pk2(0.5f * (b_ih[j] + b_hh[j]),
                  0.5f * (b_ih[HID + j] + b_hh[HID + j]));
    } else if (lane < 20) {         // (g,o) rows: g unscaled, o 0.5-folded
        const int j = lane - 10;
#pragma unroll
        for (int k = 0; k < HID; ++k)
            w2[k] = pk2(       w_hh[(2 * HID + j) * HID + k],
                        0.5f * w_hh[(3 * HID + j) * HID + k]);
        wxb = pk2(w_ih[2 * HID + j], 0.5f * w_ih[3 * HID + j]);
        bb  = pk2(        b_ih[2 * HID + j] + b_hh[2 * HID + j],
                  0.5f * (b_ih[3 * HID + j] + b_hh[3 * HID + j]));
        Alo = 1.0f; Blo = 0.0f;     // lo side is tanh(g)
    } else if (lane == 20) {        // fused fc head row
#pragma unroll
        for (int k = 0; k < HID; ++k) w2[k] = pk2(fc_w[k], 0.f);
        bb = pk2(fc_b[0], 0.f);     // wxb stays 0 -> x doesn't touch y
    }

    // ---- state ----
    ull hd[HID];                    // duplicated pairs (h_k, h_k)
#pragma unroll
    for (int k = 0; k < HID; ++k) hd[k] = 0ull;
    float c = 0.f;

    // ---- x prefetch (distance 2) ----
    float xq0 = __ldg(x + b);
    float xq1 = (S > 1) ? __ldg(x + (size_t)B + b) : xq0;

    for (int t = 0; t < S; t += 2) {
#pragma unroll
        for (int u = 0; u < 2; ++u) {
            const float xt = (u == 0) ? xq0 : xq1;
            int tn = t + u + 2; tn = (tn < S) ? tn : (S - 1);
            const float xl = __ldg(x + (size_t)tn * B + b);
            if (u == 0) xq0 = xl; else xq1 = xl;

            const ull xd = pk2(xt, xt);

            // all 40 gates + head: 11 fma2, even/odd-k split accumulators
            ull a0 = fma2(xd, wxb, bb);
            ull a1 = fma2(hd[1], w2[1], 0ull);
#pragma unroll
            for (int k = 0; k < HID; k += 2) a0 = fma2(hd[k], w2[k], a0);
#pragma unroll
            for (int k = 3; k < HID; k += 2) a1 = fma2(hd[k], w2[k], a1);
            float lo, hi;
            {
                float l0, h0, l1, h1;
                upk2(a0, l0, h0); upk2(a1, l1, h1);
                lo = l0 + l1; hi = h0 + h1;
            }
            const float yv = lo;     // lane 20: y_{t-1} (pre-activation dot)

            // activations: lanes 0-9 (sig i, sig f); 10-19 (tanh g, sig o)
            const float alo = fmaf(Alo, tanhf_hw(lo), Blo);
            const float ahi = fmaf(0.5f, tanhf_hw(hi), 0.5f);

            // bring (g,o) to lanes 0-9
            const float ga = __shfl_down_sync(0xffffffffu, alo, 10, 32);
            const float oa = __shfl_down_sync(0xffffffffu, ahi, 10, 32);

            // cell update (meaningful on lanes 0-9)
            const float cn = fmaf(alo, ga, ahi * c);
            c = cn;
            const float hn = oa * tanhf_hw(cn);

            // republish h as duplicated pairs (ping-pong buffer u)
            if (lane < 10)
                ((float2*)&hbuf[u][0])[lane] = make_float2(hn, hn);
            __syncwarp();
            {
                const float4 v0 = hbuf[u][0];
                const float4 v1 = hbuf[u][1];
                const float4 v2 = hbuf[u][2];
                const float4 v3 = hbuf[u][3];
                const float4 v4 = hbuf[u][4];
                hd[0] = pk2(v0.x, v0.y); hd[1] = pk2(v0.z, v0.w);
                hd[2] = pk2(v1.x, v1.y); hd[3] = pk2(v1.z, v1.w);
                hd[4] = pk2(v2.x, v2.y); hd[5] = pk2(v2.z, v2.w);
                hd[6] = pk2(v3.x, v3.y); hd[7] = pk2(v3.z, v3.w);
                hd[8] = pk2(v4.x, v4.y); hd[9] = pk2(v4.z, v4.w);
            }

            // head output (one step delayed)
            if (lane == 20 && (t + u) > 0)
                out[(size_t)(t + u - 1) * B + b] = yv;
        }
    }

    // epilogue: y_{S-1} from final h
    {
        ull a0 = bb;
#pragma unroll
        for (int k = 0; k < HID; ++k) a0 = fma2(hd[k], w2[k], a0);
        float lo, hi; upk2(a0, lo, hi);
        if (lane == 20)
            out[(size_t)(S - 1) * B + b] = lo;
    }
}

extern "C" void kernel_launch(void* const* d_in, const int* in_sizes, int n_in,
                              void* d_out, int out_size)
{
    const float* x    = (const float*)d_in[0];
    const float* w_ih = (const float*)d_in[1];
    const float* w_hh = (const float*)d_in[2];
    const float* b_ih = (const float*)d_in[3];
    const float* b_hh = (const float*)d_in[4];
    const float* fc_w = (const float*)d_in[5];
    const float* fc_b = (const float*)d_in[6];
    float* out = (float*)d_out;

    const int B = 4096;
    const int S = in_sizes[0] / B;   // 2048

    // one element per one-warp block -> 4096 warps, ~6.9 warps/SMSP
    lstm_wide_kernel<<<B, 32>>>(x, w_ih, w_hh, b_ih, b_hh,
                                fc_w, fc_b, out, S, B);
}

// round 10
// speedup vs baseline: 1.1101x; 1.1101x over previous
#include <cuda_runtime.h>

using ull = unsigned long long;

// ---------- packed f32x2 + MUFU helpers ----------
__device__ __forceinline__ ull pk2(float lo, float hi) {
    ull r; asm("mov.b64 %0, {%1, %2};" : "=l"(r) : "f"(lo), "f"(hi)); return r;
}
__device__ __forceinline__ void upk2(ull v, float& lo, float& hi) {
    asm("mov.b64 {%0, %1}, %2;" : "=f"(lo), "=f"(hi) : "l"(v));
}
__device__ __forceinline__ ull fma2(ull a, ull b, ull c) {
    ull d; asm("fma.rn.f32x2 %0, %1, %2, %3;" : "=l"(d) : "l"(a), "l"(b), "l"(c)); return d;
}
__device__ __forceinline__ ull add2(ull a, ull b) {
    ull d; asm("add.rn.f32x2 %0, %1, %2;" : "=l"(d) : "l"(a), "l"(b)); return d;
}
__device__ __forceinline__ float tanhf_hw(float x) {
    float y; asm("tanh.approx.f32 %0, %1;" : "=f"(y) : "f"(x)); return y;
}

#define HID 10

// TWO elements per warp (lanes 0-9 elem A, 10-19 elem B, 20-31 duplicate
// B/unit9, masked) -> 2048 warps = 3.46/SMSP. Lane j computes all 4 gates of
// unit j as TWO packed rows (i,f)/(g,o) against duplicated-h pairs that come
// straight out of LDS.128 (h stored as (hn,hn) float2 -> zero repack movs).
// Sigmoid = 0.5*(1+tanh(x/2)), 0.5 folded into i/f/o weights: 1 MUFU/gate.
// Pointer-bumped x prefetch (blind in main loop, tail peeled) kills the ALU
// index math that plagued the 1-elem/warp variant.
__global__ void __launch_bounds__(32, 16)
lstm_g2_kernel(const float* __restrict__ x,
               const float* __restrict__ w_ih,
               const float* __restrict__ w_hh,
               const float* __restrict__ b_ih,
               const float* __restrict__ b_hh,
               const float* __restrict__ fc_w,
               const float* __restrict__ fc_b,
               float* __restrict__ out,
               int S, int B)
{
    // [pingpong][group][24 floats]: 96B group stride -> the two groups'
    // broadcast LDS.128 hit disjoint banks; 16B-aligned rows.
    __shared__ __align__(16) float hsh[2][2][24];

    const int lane = threadIdx.x;
    const int wg   = blockIdx.x;

    const int grp = (lane >= HID) ? 1 : 0;        // lanes 10-31 -> group 1
    int j = lane - grp * HID; if (j >= HID) j = HID - 1;  // lanes 20-31 dup j=9

    const int b = wg * 2 + grp;                   // always < B (B even)
    const bool wr = (lane < 2 * HID) && (j == 0); // writer lanes 0 and 10

    // ---- gate-packed weights: whA=(i,f) rows, whB=(g,o) rows (0.5 fold) ----
    ull whA[HID], whB[HID];
#pragma unroll
    for (int k = 0; k < HID; ++k) {
        whA[k] = pk2(0.5f * w_hh[j * HID + k],
                     0.5f * w_hh[(HID + j) * HID + k]);
        whB[k] = pk2(       w_hh[(2 * HID + j) * HID + k],
                     0.5f * w_hh[(3 * HID + j) * HID + k]);
    }
    const ull wxA = pk2(0.5f * w_ih[j], 0.5f * w_ih[HID + j]);
    const ull wxB = pk2(       w_ih[2 * HID + j], 0.5f * w_ih[3 * HID + j]);
    const ull bA  = pk2(0.5f * (b_ih[j] + b_hh[j]),
                        0.5f * (b_ih[HID + j] + b_hh[HID + j]));
    const ull bB  = pk2(        b_ih[2 * HID + j] + b_hh[2 * HID + j],
                        0.5f * (b_ih[3 * HID + j] + b_hh[3 * HID + j]));

    float fc[HID];
#pragma unroll
    for (int k = 0; k < HID; ++k) fc[k] = fc_w[k];
    const float fb = fc_b[0];

    // ---- state: duplicated pairs (h_k, h_k) ----
    ull hd[HID];
#pragma unroll
    for (int k = 0; k < HID; ++k) hd[k] = 0ull;
    float c = 0.f;

    // ---- x prefetch: 4 in flight, pointer-bumped ----
    float xb[4];
#pragma unroll
    for (int i = 0; i < 4; ++i) xb[i] = __ldg(x + (size_t)i * B + b);
    const float* xp = x + (size_t)4 * B + b;   // next prefetch address
    float* op = out + b;

    // one LSTM step (xt in, writes y, updates hd/c); pp = ping-pong slot
#define LSTM_STEP(xt, pp)                                                    \
    {                                                                        \
        const ull xd = pk2((xt), (xt));                                      \
        ull a0 = fma2(xd, wxA, bA);                                          \
        ull q0 = fma2(xd, wxB, bB);                                          \
        ull a1 = fma2(hd[1], whA[1], 0ull);                                  \
        ull q1 = fma2(hd[1], whB[1], 0ull);                                  \
        _Pragma("unroll")                                                    \
        for (int k = 0; k < HID; k += 2) {                                   \
            a0 = fma2(hd[k], whA[k], a0);                                    \
            q0 = fma2(hd[k], whB[k], q0);                                    \
        }                                                                    \
        _Pragma("unroll")                                                    \
        for (int k = 3; k < HID; k += 2) {                                   \
            a1 = fma2(hd[k], whA[k], a1);                                    \
            q1 = fma2(hd[k], whB[k], q1);                                    \
        }                                                                    \
        float si, sf, sg, so;                                                \
        upk2(add2(a0, a1), si, sf);                                          \
        upk2(add2(q0, q1), sg, so);                                          \
        const float ia = fmaf(0.5f, tanhf_hw(si), 0.5f);                     \
        const float fa = fmaf(0.5f, tanhf_hw(sf), 0.5f);                     \
        const float ga = tanhf_hw(sg);                                       \
        const float oa = fmaf(0.5f, tanhf_hw(so), 0.5f);                     \
        const float cn = fmaf(ia, ga, fa * c);                               \
        c = cn;                                                              \
        const float hn = oa * tanhf_hw(cn);                                  \
        *(float2*)&hsh[(pp)][grp][2 * j] = make_float2(hn, hn);              \
        __syncwarp();                                                        \
        _Pragma("unroll")                                                    \
        for (int p = 0; p < 5; ++p) {                                        \
            const ulonglong2 v = *(const ulonglong2*)&hsh[(pp)][grp][4 * p]; \
            hd[2 * p]     = v.x;                                             \
            hd[2 * p + 1] = v.y;                                             \
        }                                                                    \
        float yv = fb;                                                       \
        _Pragma("unroll")                                                    \
        for (int k = 0; k < HID; ++k) {                                      \
            float lo, hi;                                                    \
            upk2(hd[k], lo, hi);                                             \
            yv = fmaf(lo, fc[k], yv);                                        \
        }                                                                    \
        if (wr) *op = yv;                                                    \
        op += B;                                                             \
    }

    // main loop: blind prefetch (reads up to x[S-1], always in-bounds)
    int t = 0;
    for (; t < S - 4; t += 4) {
#pragma unroll
        for (int u = 0; u < 4; ++u) {
            const float xt = xb[u];
            xb[u] = __ldg(xp);
            xp += B;
            LSTM_STEP(xt, u & 1);
        }
    }
    // tail: last 4 steps, no prefetch
#pragma unroll
    for (int u = 0; u < 4; ++u) {
        const float xt = xb[u];
        LSTM_STEP(xt, u & 1);
    }
#undef LSTM_STEP
}

extern "C" void kernel_launch(void* const* d_in, const int* in_sizes, int n_in,
                              void* d_out, int out_size)
{
    const float* x    = (const float*)d_in[0];
    const float* w_ih = (const float*)d_in[1];
    const float* w_hh = (const float*)d_in[2];
    const float* b_ih = (const float*)d_in[3];
    const float* b_hh = (const float*)d_in[4];
    const float* fc_w = (const float*)d_in[5];
    const float* fc_b = (const float*)d_in[6];
    float* out = (float*)d_out;

    const int B = 4096;
    const int S = in_sizes[0] / B;   // 2048

    // 2 elements per one-warp block -> 2048 warps = 3.46/SMSP
    lstm_g2_kernel<<<B / 2, 32>>>(x, w_ih, w_hh, b_ih, b_hh,
                                  fc_w, fc_b, out, S, B);
}